// round 13
// baseline (speedup 1.0000x reference)
#include <cuda_runtime.h>
#include <cuda_fp16.h>
#include <cstdint>

#define N_NODES 100000
#define N_EDGES 1600000
#define HID 64
#define CAP 128   // bucket capacity; Poisson(16) => P(deg>=128) ~ 1e-80

// ---------------- scratch (device globals; zero-initialized at load) ----------------
__device__ __half g_h16A[N_NODES * HID];
__device__ __half g_h16B[N_NODES * HID];
__device__ float  g_agg[N_NODES * HID];
__device__ int    g_csr[N_NODES * CAP];   // 51.2 MB bucketed adjacency
__device__ int    g_cnt[N_NODES];         // zeroed by last k_agg each call
__device__ int    g_is64;

// ---------------- fp16 mma helpers ----------------
__device__ __forceinline__ uint32_t pkh(float x, float y) {
    __half2 h = __floats2half2_rn(x, y);
    return *(uint32_t*)&h;
}
__device__ __forceinline__ uint32_t pklo(float x, float y, uint32_t hi) {
    __half2 h = *(__half2*)&hi;
    float2 hf = __half22float2(h);
    __half2 l = __floats2half2_rn(x - hf.x, y - hf.y);
    return *(uint32_t*)&l;
}
__device__ __forceinline__ void mma16(float* d, uint32_t a0, uint32_t a1, uint32_t a2, uint32_t a3,
                                      uint32_t b0, uint32_t b1) {
    asm volatile(
        "mma.sync.aligned.m16n8k16.row.col.f32.f16.f16.f32 "
        "{%0,%1,%2,%3},{%4,%5,%6,%7},{%8,%9},{%0,%1,%2,%3};"
        : "+f"(d[0]), "+f"(d[1]), "+f"(d[2]), "+f"(d[3])
        : "r"(a0), "r"(a1), "r"(a2), "r"(a3), "r"(b0), "r"(b1));
}

__device__ __forceinline__ int edge_at(const void* eptr, long long idx, int is64) {
    if (is64) return (int)((const long long*)eptr)[idx];
    return ((const int*)eptr)[idx];
}

// ---------------- pre-MLP (fp16 h) + edge dtype detect (block 0) ----------------
__global__ void k_pre(const float* __restrict__ x, const float* __restrict__ W,
                      const float* __restrict__ b, __half* __restrict__ h16,
                      const int* __restrict__ e32) {
    if (blockIdx.x == 0 && threadIdx.x < 32) {
        int lane = threadIdx.x;
        int bad = 0;
        for (int q = lane; q < 64; q += 32)
            if (e32[2 * q + 1] != 0) bad = 1;
        unsigned m = __ballot_sync(0xFFFFFFFFu, bad);
        if (lane == 0) g_is64 = (m == 0) ? 1 : 0;
    }
    int idx = blockIdx.x * blockDim.x + threadIdx.x;
    if (idx >= N_NODES * HID) return;
    int i = idx >> 6, j = idx & 63;
    float acc = b[j]
              + x[i * 3 + 0] * W[j * 3 + 0]
              + x[i * 3 + 1] * W[j * 3 + 1]
              + x[i * 3 + 2] * W[j * 3 + 2];
    h16[idx] = __float2half(fmaxf(acc, 0.0f));
}

// ---------------- one-pass bucketed CSR build ----------------
__global__ void k_scatter(const void* __restrict__ eptr) {
    long long e = (long long)blockIdx.x * blockDim.x + threadIdx.x;
    if (e >= N_EDGES) return;
    int is64 = g_is64;
    int s = edge_at(eptr, e, is64);
    int d = edge_at(eptr, (long long)N_EDGES + e, is64);
    int pos = atomicAdd(&g_cnt[d], 1);
    if (pos < CAP) g_csr[d * CAP + pos] = s;
}

// ---------------- aggregation: fp16 gather, fp32 accumulate ----------------
template <int LAST>
__global__ void __launch_bounds__(256) k_agg(const __half* __restrict__ h16) {
    int gtid = blockIdx.x * blockDim.x + threadIdx.x;
    int node = gtid >> 4;
    int sub = gtid & 15;
    if (node >= N_NODES) return;
    int cnt = g_cnt[node];
    if (cnt > CAP) cnt = CAP;
    const int* __restrict__ lst = &g_csr[node * CAP];
    const uint2* __restrict__ hv = (const uint2*)h16;
    float4 acc = make_float4(0.f, 0.f, 0.f, 0.f);
    int k = 0;
    for (; k + 8 <= cnt; k += 8) {
        uint2 r[8];
#pragma unroll
        for (int q = 0; q < 8; q++)
            r[q] = __ldg(&hv[lst[k + q] * 16 + sub]);
#pragma unroll
        for (int q = 0; q < 8; q++) {
            float2 f0 = __half22float2(*(__half2*)&r[q].x);
            float2 f1 = __half22float2(*(__half2*)&r[q].y);
            acc.x += f0.x; acc.y += f0.y; acc.z += f1.x; acc.w += f1.y;
        }
    }
    for (; k < cnt; k++) {
        uint2 raw = __ldg(&hv[lst[k] * 16 + sub]);
        float2 f0 = __half22float2(*(__half2*)&raw.x);
        float2 f1 = __half22float2(*(__half2*)&raw.y);
        acc.x += f0.x; acc.y += f0.y; acc.z += f1.x; acc.w += f1.y;
    }
    ((float4*)g_agg)[node * 16 + sub] = acc;
    if (LAST && sub == 0) g_cnt[node] = 0;
}

// ---------------- transform via fp16 m16n8k16 mma ----------------
// hout16 = relu([agg|h16in] @ [relW|rootW].T + relb); LAST fuses post-MLP -> out fp32.
// agg k-steps: hi/lo split (3 mmas); root k-steps: exact fp16 (2 mmas).
// B staged as PAIRED uint2 {B[kb], B[kb+4]} so each fragment fetch is one LDS.64.
// bn stride 36 uint2 (72 words = 8 mod 32): lane bank = 8*qr + 2*qc -> conflict-free.
#define BSTR 36
#define SPAD 66
#define XF_SMEM0 (2 * 64 * BSTR * 8)                       // 36864 B
#define XF_SMEM1 (2 * 64 * BSTR * 8 + 8 * 16 * SPAD * 4)   // 70656 B

template <int LAST>
__global__ void __launch_bounds__(256, 3) k_xf(
        const __half* __restrict__ h16in,
        const float* __restrict__ relW, const float* __restrict__ relb,
        const float* __restrict__ rootW,
        const float* __restrict__ postW, const float* __restrict__ postb,
        float* __restrict__ out, __half* __restrict__ hout16) {
    extern __shared__ uint2 smem2[];
    uint2* sBh2 = smem2;                   // [bn][ks][qc] paired hi
    uint2* sBl2 = smem2 + 64 * BSTR;       // paired lo
    float* sSt = (float*)(smem2 + 2 * 64 * BSTR);   // LAST only
    const int tid = threadIdx.x;
    const int warp = tid >> 5;
    const int lane = tid & 31;

    // --- stage combined weights as paired hi/lo: entry (n, ks, qc) = {W2[kp], W2[kp+4]} ---
    for (int idx = tid; idx < 64 * 32; idx += 256) {
        int n = idx >> 5;
        int rem = idx & 31;
        int ks = rem >> 2, qc = rem & 3;
        int kp = ks * 8 + qc;
        int k0 = kp * 2;          // first pair: halves k0, k0+1
        int k1 = k0 + 8;          // second pair: halves k1, k1+1 (kp+4)
        float2 v0 = (k0 < 64) ? *(const float2*)&relW[n * 64 + k0]
                              : *(const float2*)&rootW[n * 64 + (k0 - 64)];
        float2 v1 = (k1 < 64) ? *(const float2*)&relW[n * 64 + k1]
                              : *(const float2*)&rootW[n * 64 + (k1 - 64)];
        uint32_t hi0 = pkh(v0.x, v0.y);
        uint32_t hi1 = pkh(v1.x, v1.y);
        int e = n * BSTR + ks * 4 + qc;
        sBh2[e] = make_uint2(hi0, hi1);
        sBl2[e] = make_uint2(pklo(v0.x, v0.y, hi0), pklo(v1.x, v1.y, hi1));
    }
    __syncthreads();

    const int qr = lane >> 2;
    const int qc = lane & 3;
    const int r0 = blockIdx.x * 128 + warp * 16 + qr;
    const int r1 = r0 + 8;
    const int r0c = (r0 < N_NODES) ? r0 : (N_NODES - 1);
    const int r1c = (r1 < N_NODES) ? r1 : (N_NODES - 1);
    const float* __restrict__ aggr0 = &g_agg[(size_t)r0c * 64];
    const float* __restrict__ aggr1 = &g_agg[(size_t)r1c * 64];
    const __half* __restrict__ hr0 = &h16in[(size_t)r0c * 64];
    const __half* __restrict__ hr1 = &h16in[(size_t)r1c * 64];

    float d[8][4];
#pragma unroll
    for (int nt = 0; nt < 8; nt++)
#pragma unroll
        for (int i = 0; i < 4; i++) d[nt][i] = 0.f;

    // --- software-pipelined agg k-steps (ks 0..3): hi/lo split, 3 mmas ---
    float2 pa0 = __ldg((const float2*)&aggr0[2 * qc]);
    float2 pa1 = __ldg((const float2*)&aggr1[2 * qc]);
    float2 pa2 = __ldg((const float2*)&aggr0[2 * qc + 8]);
    float2 pa3 = __ldg((const float2*)&aggr1[2 * qc + 8]);
    uint32_t pr0, pr1, pr2, pr3;
#pragma unroll
    for (int ks = 0; ks < 4; ks++) {
        float2 f0 = pa0, f1 = pa1, f2 = pa2, f3 = pa3;
        if (ks < 3) {
            const int kc = (ks + 1) * 16 + 2 * qc;
            pa0 = __ldg((const float2*)&aggr0[kc]);
            pa1 = __ldg((const float2*)&aggr1[kc]);
            pa2 = __ldg((const float2*)&aggr0[kc + 8]);
            pa3 = __ldg((const float2*)&aggr1[kc + 8]);
        } else {
            const int kc = 2 * qc;
            pr0 = __ldg((const uint32_t*)&hr0[kc]);
            pr1 = __ldg((const uint32_t*)&hr1[kc]);
            pr2 = __ldg((const uint32_t*)&hr0[kc + 8]);
            pr3 = __ldg((const uint32_t*)&hr1[kc + 8]);
        }
        uint32_t ah0 = pkh(f0.x, f0.y), ah1 = pkh(f1.x, f1.y);
        uint32_t ah2 = pkh(f2.x, f2.y), ah3 = pkh(f3.x, f3.y);
        uint32_t al0 = pklo(f0.x, f0.y, ah0), al1 = pklo(f1.x, f1.y, ah1);
        uint32_t al2 = pklo(f2.x, f2.y, ah2), al3 = pklo(f3.x, f3.y, ah3);

        const int eb = ks * 4 + qc;
#pragma unroll
        for (int nt = 0; nt < 8; nt++) {
            const int e = (nt * 8 + qr) * BSTR + eb;
            uint2 bh = sBh2[e];
            uint2 bl = sBl2[e];
            mma16(d[nt], ah0, ah1, ah2, ah3, bh.x, bh.y);
            mma16(d[nt], al0, al1, al2, al3, bh.x, bh.y);
            mma16(d[nt], ah0, ah1, ah2, ah3, bl.x, bl.y);
        }
    }

    // --- software-pipelined root k-steps (ks 4..7): exact fp16, 2 mmas ---
#pragma unroll
    for (int ks = 4; ks < 8; ks++) {
        uint32_t ah0 = pr0, ah1 = pr1, ah2 = pr2, ah3 = pr3;
        if (ks < 7) {
            const int kc = (ks - 3) * 16 + 2 * qc;
            pr0 = __ldg((const uint32_t*)&hr0[kc]);
            pr1 = __ldg((const uint32_t*)&hr1[kc]);
            pr2 = __ldg((const uint32_t*)&hr0[kc + 8]);
            pr3 = __ldg((const uint32_t*)&hr1[kc + 8]);
        }
        const int eb = ks * 4 + qc;
#pragma unroll
        for (int nt = 0; nt < 8; nt++) {
            const int e = (nt * 8 + qr) * BSTR + eb;
            uint2 bh = sBh2[e];
            uint2 bl = sBl2[e];
            mma16(d[nt], ah0, ah1, ah2, ah3, bh.x, bh.y);
            mma16(d[nt], ah0, ah1, ah2, ah3, bl.x, bl.y);
        }
    }

    if (!LAST) {
#pragma unroll
        for (int nt = 0; nt < 8; nt++) {
            const int col = nt * 8 + 2 * qc;
            const float bx = __ldg(&relb[col]);
            const float by = __ldg(&relb[col + 1]);
            if (r0 < N_NODES) {
                float vx = fmaxf(d[nt][0] + bx, 0.f), vy = fmaxf(d[nt][1] + by, 0.f);
                *(__half2*)&hout16[(size_t)r0 * 64 + col] = __floats2half2_rn(vx, vy);
            }
            if (r1 < N_NODES) {
                float vx = fmaxf(d[nt][2] + bx, 0.f), vy = fmaxf(d[nt][3] + by, 0.f);
                *(__half2*)&hout16[(size_t)r1 * 64 + col] = __floats2half2_rn(vx, vy);
            }
        }
    } else {
        float* st = sSt + warp * 16 * SPAD;
#pragma unroll
        for (int nt = 0; nt < 8; nt++) {
            const int col = nt * 8 + 2 * qc;
            const float bx = __ldg(&relb[col]);
            const float by = __ldg(&relb[col + 1]);
            st[qr * SPAD + col]           = fmaxf(d[nt][0] + bx, 0.f);
            st[qr * SPAD + col + 1]       = fmaxf(d[nt][1] + by, 0.f);
            st[(qr + 8) * SPAD + col]     = fmaxf(d[nt][2] + bx, 0.f);
            st[(qr + 8) * SPAD + col + 1] = fmaxf(d[nt][3] + by, 0.f);
        }
        __syncwarp();
        if (lane < 16) {
            const int gr = blockIdx.x * 128 + warp * 16 + lane;
            if (gr < N_NODES) {
                float o0 = __ldg(&postb[0]), o1 = __ldg(&postb[1]);
                const float* row = &st[lane * SPAD];
#pragma unroll 8
                for (int c = 0; c < 64; c++) {
                    float v = row[c];
                    o0 += v * __ldg(&postW[c]);
                    o1 += v * __ldg(&postW[64 + c]);
                }
                out[2 * gr + 0] = fmaxf(o0, 0.f);
                out[2 * gr + 1] = fmaxf(o1, 0.f);
            }
        }
    }
}

// ---------------- launch (8 kernels) ----------------
extern "C" void kernel_launch(void* const* d_in, const int* in_sizes, int n_in,
                              void* d_out, int out_size) {
    const float* x     = (const float*)d_in[0];
    const void*  ei    = d_in[1];
    const float* preW  = (const float*)d_in[2];
    const float* preb  = (const float*)d_in[3];
    const float* postW = (const float*)d_in[4];
    const float* postb = (const float*)d_in[5];
    const float* relW[3]  = {(const float*)d_in[6],  (const float*)d_in[9],  (const float*)d_in[12]};
    const float* relb[3]  = {(const float*)d_in[7],  (const float*)d_in[10], (const float*)d_in[13]};
    const float* rootW[3] = {(const float*)d_in[8],  (const float*)d_in[11], (const float*)d_in[14]};
    float* out = (float*)d_out;

    cudaFuncSetAttribute(k_xf<0>, cudaFuncAttributeMaxDynamicSharedMemorySize, XF_SMEM0);
    cudaFuncSetAttribute(k_xf<1>, cudaFuncAttributeMaxDynamicSharedMemorySize, XF_SMEM1);

    __half *h16A, *h16B;
    cudaGetSymbolAddress((void**)&h16A, g_h16A);
    cudaGetSymbolAddress((void**)&h16B, g_h16B);

    // 1. pre-MLP (+ edge dtype detect in block 0)
    k_pre<<<(N_NODES * HID + 255) / 256, 256>>>(x, preW, preb, h16A, (const int*)ei);
    // 2. one-pass bucketed CSR build
    k_scatter<<<(N_EDGES + 255) / 256, 256>>>(ei);

    const int agg_blocks = (N_NODES * 16 + 255) / 256;
    const int xf_blocks  = (N_NODES + 127) / 128;

    // 3-8. layer 0: A -> B ; layer 1: B -> A ; layer 2 (last, fused post): A -> out
    k_agg<0><<<agg_blocks, 256>>>(h16A);
    k_xf<0><<<xf_blocks, 256, XF_SMEM0>>>(h16A, relW[0], relb[0], rootW[0], postW, postb, out, h16B);
    k_agg<0><<<agg_blocks, 256>>>(h16B);
    k_xf<0><<<xf_blocks, 256, XF_SMEM0>>>(h16B, relW[1], relb[1], rootW[1], postW, postb, out, h16A);
    k_agg<1><<<agg_blocks, 256>>>(h16A);   // zeros g_cnt after final read
    k_xf<1><<<xf_blocks, 256, XF_SMEM1>>>(h16A, relW[2], relb[2], rootW[2], postW, postb, out, h16B);
}

// round 14
// speedup vs baseline: 1.0206x; 1.0206x over previous
#include <cuda_runtime.h>
#include <cuda_fp16.h>
#include <cstdint>

#define N_NODES 100000
#define N_EDGES 1600000
#define HID 64
#define CAP 128   // bucket capacity; Poisson(16) => P(deg>=128) ~ 1e-80

// ---------------- scratch (device globals; zero-initialized at load) ----------------
__device__ __half g_h16A[N_NODES * HID];
__device__ __half g_h16B[N_NODES * HID];
__device__ float  g_agg[N_NODES * HID];
__device__ int    g_csr[N_NODES * CAP];   // 51.2 MB bucketed adjacency
__device__ int    g_cnt[N_NODES];         // zeroed by last k_agg each call
__device__ int    g_is64;

// ---------------- fp16 mma helpers ----------------
__device__ __forceinline__ uint32_t pkh(float x, float y) {
    __half2 h = __floats2half2_rn(x, y);
    return *(uint32_t*)&h;
}
__device__ __forceinline__ uint32_t pklo(float x, float y, uint32_t hi) {
    __half2 h = *(__half2*)&hi;
    float2 hf = __half22float2(h);
    __half2 l = __floats2half2_rn(x - hf.x, y - hf.y);
    return *(uint32_t*)&l;
}
__device__ __forceinline__ void mma16(float* d, uint32_t a0, uint32_t a1, uint32_t a2, uint32_t a3,
                                      uint32_t b0, uint32_t b1) {
    asm volatile(
        "mma.sync.aligned.m16n8k16.row.col.f32.f16.f16.f32 "
        "{%0,%1,%2,%3},{%4,%5,%6,%7},{%8,%9},{%0,%1,%2,%3};"
        : "+f"(d[0]), "+f"(d[1]), "+f"(d[2]), "+f"(d[3])
        : "r"(a0), "r"(a1), "r"(a2), "r"(a3), "r"(b0), "r"(b1));
}

__device__ __forceinline__ int edge_at(const void* eptr, long long idx, int is64) {
    if (is64) return (int)((const long long*)eptr)[idx];
    return ((const int*)eptr)[idx];
}

// ---------------- pre-MLP (fp16 h) + edge dtype detect (block 0) ----------------
__global__ void k_pre(const float* __restrict__ x, const float* __restrict__ W,
                      const float* __restrict__ b, __half* __restrict__ h16,
                      const int* __restrict__ e32) {
    if (blockIdx.x == 0 && threadIdx.x < 32) {
        int lane = threadIdx.x;
        int bad = 0;
        for (int q = lane; q < 64; q += 32)
            if (e32[2 * q + 1] != 0) bad = 1;
        unsigned m = __ballot_sync(0xFFFFFFFFu, bad);
        if (lane == 0) g_is64 = (m == 0) ? 1 : 0;
    }
    int idx = blockIdx.x * blockDim.x + threadIdx.x;
    if (idx >= N_NODES * HID) return;
    int i = idx >> 6, j = idx & 63;
    float acc = b[j]
              + x[i * 3 + 0] * W[j * 3 + 0]
              + x[i * 3 + 1] * W[j * 3 + 1]
              + x[i * 3 + 2] * W[j * 3 + 2];
    h16[idx] = __float2half(fmaxf(acc, 0.0f));
}

// ---------------- one-pass bucketed CSR build ----------------
__global__ void k_scatter(const void* __restrict__ eptr) {
    long long e = (long long)blockIdx.x * blockDim.x + threadIdx.x;
    if (e >= N_EDGES) return;
    int is64 = g_is64;
    int s = edge_at(eptr, e, is64);
    int d = edge_at(eptr, (long long)N_EDGES + e, is64);
    int pos = atomicAdd(&g_cnt[d], 1);
    if (pos < CAP) g_csr[d * CAP + pos] = s;
}

// ---------------- aggregation: fp16 gather, fp32 accumulate ----------------
template <int LAST>
__global__ void __launch_bounds__(256) k_agg(const __half* __restrict__ h16) {
    int gtid = blockIdx.x * blockDim.x + threadIdx.x;
    int node = gtid >> 4;
    int sub = gtid & 15;
    if (node >= N_NODES) return;
    int cnt = g_cnt[node];
    if (cnt > CAP) cnt = CAP;
    const int* __restrict__ lst = &g_csr[node * CAP];
    const uint2* __restrict__ hv = (const uint2*)h16;
    float4 acc = make_float4(0.f, 0.f, 0.f, 0.f);
    int k = 0;
    for (; k + 8 <= cnt; k += 8) {
        uint2 r[8];
#pragma unroll
        for (int q = 0; q < 8; q++)
            r[q] = __ldg(&hv[lst[k + q] * 16 + sub]);
#pragma unroll
        for (int q = 0; q < 8; q++) {
            float2 f0 = __half22float2(*(__half2*)&r[q].x);
            float2 f1 = __half22float2(*(__half2*)&r[q].y);
            acc.x += f0.x; acc.y += f0.y; acc.z += f1.x; acc.w += f1.y;
        }
    }
    for (; k < cnt; k++) {
        uint2 raw = __ldg(&hv[lst[k] * 16 + sub]);
        float2 f0 = __half22float2(*(__half2*)&raw.x);
        float2 f1 = __half22float2(*(__half2*)&raw.y);
        acc.x += f0.x; acc.y += f0.y; acc.z += f1.x; acc.w += f1.y;
    }
    ((float4*)g_agg)[node * 16 + sub] = acc;
    if (LAST && sub == 0) g_cnt[node] = 0;
}

// ================= transform kernels (fp16 m16n8k16, hi/lo split) =================
// agg k-steps: 3 mmas (A hi/lo x B hi); root k-steps: 2 mmas (A exact fp16).
#define WPAD 68
#define SPAD 66

// ---- non-last: column-split. blockIdx = rowtile*2 + colhalf; 4 n-tiles per warp ----
#define XFS_SMEM (2 * 32 * WPAD * 4)   // 17408 B

__global__ void __launch_bounds__(256, 4) k_xfs(
        const __half* __restrict__ h16in,
        const float* __restrict__ relW, const float* __restrict__ relb,
        const float* __restrict__ rootW,
        __half* __restrict__ hout16) {
    extern __shared__ uint32_t smemu[];
    uint32_t* sBh = smemu;               // [32 n][64 kp] stride WPAD (local n)
    uint32_t* sBl = smemu + 32 * WPAD;
    const int tid = threadIdx.x;
    const int warp = tid >> 5;
    const int lane = tid & 31;
    const int rowtile = blockIdx.x >> 1;
    const int half = blockIdx.x & 1;
    const int nbase = half * 32;

    // --- stage this half's 32 weight rows as packed half2 hi/lo ---
    for (int f = tid; f < 32 * 32; f += 256) {
        int nl = f >> 5, kp2 = (f & 31) * 2;
        int n = nbase + nl;
        int k = kp2 * 2;
        const float* src = (k < 64) ? &relW[n * 64 + k] : &rootW[n * 64 + (k - 64)];
        float4 v = *(const float4*)src;
        uint32_t hi0 = pkh(v.x, v.y);
        uint32_t hi1 = pkh(v.z, v.w);
        sBh[nl * WPAD + kp2]     = hi0;
        sBh[nl * WPAD + kp2 + 1] = hi1;
        sBl[nl * WPAD + kp2]     = pklo(v.x, v.y, hi0);
        sBl[nl * WPAD + kp2 + 1] = pklo(v.z, v.w, hi1);
    }
    __syncthreads();

    const int qr = lane >> 2;
    const int qc = lane & 3;
    const int r0 = rowtile * 128 + warp * 16 + qr;
    const int r1 = r0 + 8;
    const int r0c = (r0 < N_NODES) ? r0 : (N_NODES - 1);
    const int r1c = (r1 < N_NODES) ? r1 : (N_NODES - 1);
    const float* __restrict__ aggr0 = &g_agg[(size_t)r0c * 64];
    const float* __restrict__ aggr1 = &g_agg[(size_t)r1c * 64];
    const __half* __restrict__ hr0 = &h16in[(size_t)r0c * 64];
    const __half* __restrict__ hr1 = &h16in[(size_t)r1c * 64];

    float d[4][4];
#pragma unroll
    for (int nt = 0; nt < 4; nt++)
#pragma unroll
        for (int i = 0; i < 4; i++) d[nt][i] = 0.f;

    // --- software-pipelined agg k-steps (ks 0..3) ---
    float2 pa0 = __ldg((const float2*)&aggr0[2 * qc]);
    float2 pa1 = __ldg((const float2*)&aggr1[2 * qc]);
    float2 pa2 = __ldg((const float2*)&aggr0[2 * qc + 8]);
    float2 pa3 = __ldg((const float2*)&aggr1[2 * qc + 8]);
    uint32_t pr0, pr1, pr2, pr3;
#pragma unroll
    for (int ks = 0; ks < 4; ks++) {
        float2 f0 = pa0, f1 = pa1, f2 = pa2, f3 = pa3;
        if (ks < 3) {
            const int kc = (ks + 1) * 16 + 2 * qc;
            pa0 = __ldg((const float2*)&aggr0[kc]);
            pa1 = __ldg((const float2*)&aggr1[kc]);
            pa2 = __ldg((const float2*)&aggr0[kc + 8]);
            pa3 = __ldg((const float2*)&aggr1[kc + 8]);
        } else {
            const int kc = 2 * qc;
            pr0 = __ldg((const uint32_t*)&hr0[kc]);
            pr1 = __ldg((const uint32_t*)&hr1[kc]);
            pr2 = __ldg((const uint32_t*)&hr0[kc + 8]);
            pr3 = __ldg((const uint32_t*)&hr1[kc + 8]);
        }
        uint32_t ah0 = pkh(f0.x, f0.y), ah1 = pkh(f1.x, f1.y);
        uint32_t ah2 = pkh(f2.x, f2.y), ah3 = pkh(f3.x, f3.y);
        uint32_t al0 = pklo(f0.x, f0.y, ah0), al1 = pklo(f1.x, f1.y, ah1);
        uint32_t al2 = pklo(f2.x, f2.y, ah2), al3 = pklo(f3.x, f3.y, ah3);

        const int kb = ks * 8 + qc;
#pragma unroll
        for (int nt = 0; nt < 4; nt++) {
            const int bn = nt * 8 + qr;   // local n row
            uint32_t bh0 = sBh[bn * WPAD + kb];
            uint32_t bh1 = sBh[bn * WPAD + kb + 4];
            uint32_t bl0 = sBl[bn * WPAD + kb];
            uint32_t bl1 = sBl[bn * WPAD + kb + 4];
            mma16(d[nt], ah0, ah1, ah2, ah3, bh0, bh1);
            mma16(d[nt], al0, al1, al2, al3, bh0, bh1);
            mma16(d[nt], ah0, ah1, ah2, ah3, bl0, bl1);
        }
    }

    // --- software-pipelined root k-steps (ks 4..7) ---
#pragma unroll
    for (int ks = 4; ks < 8; ks++) {
        uint32_t ah0 = pr0, ah1 = pr1, ah2 = pr2, ah3 = pr3;
        if (ks < 7) {
            const int kc = (ks - 3) * 16 + 2 * qc;
            pr0 = __ldg((const uint32_t*)&hr0[kc]);
            pr1 = __ldg((const uint32_t*)&hr1[kc]);
            pr2 = __ldg((const uint32_t*)&hr0[kc + 8]);
            pr3 = __ldg((const uint32_t*)&hr1[kc + 8]);
        }
        const int kb = ks * 8 + qc;
#pragma unroll
        for (int nt = 0; nt < 4; nt++) {
            const int bn = nt * 8 + qr;
            uint32_t bh0 = sBh[bn * WPAD + kb];
            uint32_t bh1 = sBh[bn * WPAD + kb + 4];
            uint32_t bl0 = sBl[bn * WPAD + kb];
            uint32_t bl1 = sBl[bn * WPAD + kb + 4];
            mma16(d[nt], ah0, ah1, ah2, ah3, bh0, bh1);
            mma16(d[nt], ah0, ah1, ah2, ah3, bl0, bl1);
        }
    }

#pragma unroll
    for (int nt = 0; nt < 4; nt++) {
        const int col = nbase + nt * 8 + 2 * qc;
        const float bx = __ldg(&relb[col]);
        const float by = __ldg(&relb[col + 1]);
        if (r0 < N_NODES) {
            float vx = fmaxf(d[nt][0] + bx, 0.f), vy = fmaxf(d[nt][1] + by, 0.f);
            *(__half2*)&hout16[(size_t)r0 * 64 + col] = __floats2half2_rn(vx, vy);
        }
        if (r1 < N_NODES) {
            float vx = fmaxf(d[nt][2] + bx, 0.f), vy = fmaxf(d[nt][3] + by, 0.f);
            *(__half2*)&hout16[(size_t)r1 * 64 + col] = __floats2half2_rn(vx, vy);
        }
    }
}

// ---- last layer: full 64 cols per block + fused post-MLP (R12 form) ----
#define XFL_SMEM (2 * 64 * WPAD * 4 + 8 * 16 * SPAD * 4)   // 68608 B

__global__ void __launch_bounds__(256, 3) k_xfl(
        const __half* __restrict__ h16in,
        const float* __restrict__ relW, const float* __restrict__ relb,
        const float* __restrict__ rootW,
        const float* __restrict__ postW, const float* __restrict__ postb,
        float* __restrict__ out) {
    extern __shared__ uint32_t smemu[];
    uint32_t* sBh = smemu;
    uint32_t* sBl = smemu + 64 * WPAD;
    float* sSt = (float*)(smemu + 2 * 64 * WPAD);
    const int tid = threadIdx.x;
    const int warp = tid >> 5;
    const int lane = tid & 31;

    for (int f = tid; f < 64 * 32; f += 256) {
        int n = f >> 5, kp2 = (f & 31) * 2;
        int k = kp2 * 2;
        const float* src = (k < 64) ? &relW[n * 64 + k] : &rootW[n * 64 + (k - 64)];
        float4 v = *(const float4*)src;
        uint32_t hi0 = pkh(v.x, v.y);
        uint32_t hi1 = pkh(v.z, v.w);
        sBh[n * WPAD + kp2]     = hi0;
        sBh[n * WPAD + kp2 + 1] = hi1;
        sBl[n * WPAD + kp2]     = pklo(v.x, v.y, hi0);
        sBl[n * WPAD + kp2 + 1] = pklo(v.z, v.w, hi1);
    }
    __syncthreads();

    const int qr = lane >> 2;
    const int qc = lane & 3;
    const int r0 = blockIdx.x * 128 + warp * 16 + qr;
    const int r1 = r0 + 8;
    const int r0c = (r0 < N_NODES) ? r0 : (N_NODES - 1);
    const int r1c = (r1 < N_NODES) ? r1 : (N_NODES - 1);
    const float* __restrict__ aggr0 = &g_agg[(size_t)r0c * 64];
    const float* __restrict__ aggr1 = &g_agg[(size_t)r1c * 64];
    const __half* __restrict__ hr0 = &h16in[(size_t)r0c * 64];
    const __half* __restrict__ hr1 = &h16in[(size_t)r1c * 64];

    float d[8][4];
#pragma unroll
    for (int nt = 0; nt < 8; nt++)
#pragma unroll
        for (int i = 0; i < 4; i++) d[nt][i] = 0.f;

    float2 pa0 = __ldg((const float2*)&aggr0[2 * qc]);
    float2 pa1 = __ldg((const float2*)&aggr1[2 * qc]);
    float2 pa2 = __ldg((const float2*)&aggr0[2 * qc + 8]);
    float2 pa3 = __ldg((const float2*)&aggr1[2 * qc + 8]);
    uint32_t pr0, pr1, pr2, pr3;
#pragma unroll
    for (int ks = 0; ks < 4; ks++) {
        float2 f0 = pa0, f1 = pa1, f2 = pa2, f3 = pa3;
        if (ks < 3) {
            const int kc = (ks + 1) * 16 + 2 * qc;
            pa0 = __ldg((const float2*)&aggr0[kc]);
            pa1 = __ldg((const float2*)&aggr1[kc]);
            pa2 = __ldg((const float2*)&aggr0[kc + 8]);
            pa3 = __ldg((const float2*)&aggr1[kc + 8]);
        } else {
            const int kc = 2 * qc;
            pr0 = __ldg((const uint32_t*)&hr0[kc]);
            pr1 = __ldg((const uint32_t*)&hr1[kc]);
            pr2 = __ldg((const uint32_t*)&hr0[kc + 8]);
            pr3 = __ldg((const uint32_t*)&hr1[kc + 8]);
        }
        uint32_t ah0 = pkh(f0.x, f0.y), ah1 = pkh(f1.x, f1.y);
        uint32_t ah2 = pkh(f2.x, f2.y), ah3 = pkh(f3.x, f3.y);
        uint32_t al0 = pklo(f0.x, f0.y, ah0), al1 = pklo(f1.x, f1.y, ah1);
        uint32_t al2 = pklo(f2.x, f2.y, ah2), al3 = pklo(f3.x, f3.y, ah3);

        const int kb = ks * 8 + qc;
#pragma unroll
        for (int nt = 0; nt < 8; nt++) {
            const int bn = nt * 8 + qr;
            uint32_t bh0 = sBh[bn * WPAD + kb];
            uint32_t bh1 = sBh[bn * WPAD + kb + 4];
            uint32_t bl0 = sBl[bn * WPAD + kb];
            uint32_t bl1 = sBl[bn * WPAD + kb + 4];
            mma16(d[nt], ah0, ah1, ah2, ah3, bh0, bh1);
            mma16(d[nt], al0, al1, al2, al3, bh0, bh1);
            mma16(d[nt], ah0, ah1, ah2, ah3, bl0, bl1);
        }
    }

#pragma unroll
    for (int ks = 4; ks < 8; ks++) {
        uint32_t ah0 = pr0, ah1 = pr1, ah2 = pr2, ah3 = pr3;
        if (ks < 7) {
            const int kc = (ks - 3) * 16 + 2 * qc;
            pr0 = __ldg((const uint32_t*)&hr0[kc]);
            pr1 = __ldg((const uint32_t*)&hr1[kc]);
            pr2 = __ldg((const uint32_t*)&hr0[kc + 8]);
            pr3 = __ldg((const uint32_t*)&hr1[kc + 8]);
        }
        const int kb = ks * 8 + qc;
#pragma unroll
        for (int nt = 0; nt < 8; nt++) {
            const int bn = nt * 8 + qr;
            uint32_t bh0 = sBh[bn * WPAD + kb];
            uint32_t bh1 = sBh[bn * WPAD + kb + 4];
            uint32_t bl0 = sBl[bn * WPAD + kb];
            uint32_t bl1 = sBl[bn * WPAD + kb + 4];
            mma16(d[nt], ah0, ah1, ah2, ah3, bh0, bh1);
            mma16(d[nt], ah0, ah1, ah2, ah3, bl0, bl1);
        }
    }

    float* st = sSt + warp * 16 * SPAD;
#pragma unroll
    for (int nt = 0; nt < 8; nt++) {
        const int col = nt * 8 + 2 * qc;
        const float bx = __ldg(&relb[col]);
        const float by = __ldg(&relb[col + 1]);
        st[qr * SPAD + col]           = fmaxf(d[nt][0] + bx, 0.f);
        st[qr * SPAD + col + 1]       = fmaxf(d[nt][1] + by, 0.f);
        st[(qr + 8) * SPAD + col]     = fmaxf(d[nt][2] + bx, 0.f);
        st[(qr + 8) * SPAD + col + 1] = fmaxf(d[nt][3] + by, 0.f);
    }
    __syncwarp();
    if (lane < 16) {
        const int gr = blockIdx.x * 128 + warp * 16 + lane;
        if (gr < N_NODES) {
            float o0 = __ldg(&postb[0]), o1 = __ldg(&postb[1]);
            const float* row = &st[lane * SPAD];
#pragma unroll 8
            for (int c = 0; c < 64; c++) {
                float v = row[c];
                o0 += v * __ldg(&postW[c]);
                o1 += v * __ldg(&postW[64 + c]);
            }
            out[2 * gr + 0] = fmaxf(o0, 0.f);
            out[2 * gr + 1] = fmaxf(o1, 0.f);
        }
    }
}

// ---------------- launch (8 kernels) ----------------
extern "C" void kernel_launch(void* const* d_in, const int* in_sizes, int n_in,
                              void* d_out, int out_size) {
    const float* x     = (const float*)d_in[0];
    const void*  ei    = d_in[1];
    const float* preW  = (const float*)d_in[2];
    const float* preb  = (const float*)d_in[3];
    const float* postW = (const float*)d_in[4];
    const float* postb = (const float*)d_in[5];
    const float* relW[3]  = {(const float*)d_in[6],  (const float*)d_in[9],  (const float*)d_in[12]};
    const float* relb[3]  = {(const float*)d_in[7],  (const float*)d_in[10], (const float*)d_in[13]};
    const float* rootW[3] = {(const float*)d_in[8],  (const float*)d_in[11], (const float*)d_in[14]};
    float* out = (float*)d_out;

    cudaFuncSetAttribute(k_xfs, cudaFuncAttributeMaxDynamicSharedMemorySize, XFS_SMEM);
    cudaFuncSetAttribute(k_xfl, cudaFuncAttributeMaxDynamicSharedMemorySize, XFL_SMEM);

    __half *h16A, *h16B;
    cudaGetSymbolAddress((void**)&h16A, g_h16A);
    cudaGetSymbolAddress((void**)&h16B, g_h16B);

    // 1. pre-MLP (+ edge dtype detect in block 0)
    k_pre<<<(N_NODES * HID + 255) / 256, 256>>>(x, preW, preb, h16A, (const int*)ei);
    // 2. one-pass bucketed CSR build
    k_scatter<<<(N_EDGES + 255) / 256, 256>>>(ei);

    const int agg_blocks = (N_NODES * 16 + 255) / 256;
    const int xf_tiles   = (N_NODES + 127) / 128;

    // 3-8. layer 0: A -> B ; layer 1: B -> A ; layer 2 (last, fused post): A -> out
    k_agg<0><<<agg_blocks, 256>>>(h16A);
    k_xfs<<<xf_tiles * 2, 256, XFS_SMEM>>>(h16A, relW[0], relb[0], rootW[0], h16B);
    k_agg<0><<<agg_blocks, 256>>>(h16B);
    k_xfs<<<xf_tiles * 2, 256, XFS_SMEM>>>(h16B, relW[1], relb[1], rootW[1], h16A);
    k_agg<1><<<agg_blocks, 256>>>(h16A);   // zeros g_cnt after final read
    k_xfl<<<xf_tiles, 256, XFL_SMEM>>>(h16A, relW[2], relb[2], rootW[2], postW, postb, out);
}

// round 16
// speedup vs baseline: 1.0614x; 1.0399x over previous
#include <cuda_runtime.h>
#include <cuda_fp16.h>
#include <cstdint>

#define N_NODES 100000
#define N_EDGES 1600000
#define HID 64
#define CAP 128   // bucket capacity; Poisson(16) => P(deg>=128) ~ 1e-80

// ---------------- scratch (device globals; zero-initialized at load) ----------------
__device__ __half g_h16A[N_NODES * HID];
__device__ __half g_h16B[N_NODES * HID];
__device__ float  g_agg[N_NODES * HID];
__device__ int    g_csr[N_NODES * CAP];   // 51.2 MB bucketed adjacency
__device__ int    g_cnt[N_NODES];         // zeroed by last k_agg each call
__device__ int    g_is64;

// ---------------- fp16 mma helpers ----------------
__device__ __forceinline__ uint32_t pkh(float x, float y) {
    __half2 h = __floats2half2_rn(x, y);
    return *(uint32_t*)&h;
}
__device__ __forceinline__ uint32_t pklo(float x, float y, uint32_t hi) {
    __half2 h = *(__half2*)&hi;
    float2 hf = __half22float2(h);
    __half2 l = __floats2half2_rn(x - hf.x, y - hf.y);
    return *(uint32_t*)&l;
}
__device__ __forceinline__ void mma16(float* d, uint32_t a0, uint32_t a1, uint32_t a2, uint32_t a3,
                                      uint32_t b0, uint32_t b1) {
    asm volatile(
        "mma.sync.aligned.m16n8k16.row.col.f32.f16.f16.f32 "
        "{%0,%1,%2,%3},{%4,%5,%6,%7},{%8,%9},{%0,%1,%2,%3};"
        : "+f"(d[0]), "+f"(d[1]), "+f"(d[2]), "+f"(d[3])
        : "r"(a0), "r"(a1), "r"(a2), "r"(a3), "r"(b0), "r"(b1));
}
// ldmatrix x4: four 8x8 b16 matrices; lane groups of 8 supply row addresses
#define LDSM_X4(r0, r1, r2, r3, addr) \
    asm volatile("ldmatrix.sync.aligned.m8n8.x4.shared.b16 {%0,%1,%2,%3}, [%4];" \
                 : "=r"(r0), "=r"(r1), "=r"(r2), "=r"(r3) : "r"(addr))

__device__ __forceinline__ uint32_t smem_u32(const void* p) {
    return (uint32_t)__cvta_generic_to_shared(p);
}

__device__ __forceinline__ int edge_at(const void* eptr, long long idx, int is64) {
    if (is64) return (int)((const long long*)eptr)[idx];
    return ((const int*)eptr)[idx];
}

// ---------------- pre-MLP (fp16 h) + edge dtype detect (block 0) ----------------
__global__ void k_pre(const float* __restrict__ x, const float* __restrict__ W,
                      const float* __restrict__ b, __half* __restrict__ h16,
                      const int* __restrict__ e32) {
    if (blockIdx.x == 0 && threadIdx.x < 32) {
        int lane = threadIdx.x;
        int bad = 0;
        for (int q = lane; q < 64; q += 32)
            if (e32[2 * q + 1] != 0) bad = 1;
        unsigned m = __ballot_sync(0xFFFFFFFFu, bad);
        if (lane == 0) g_is64 = (m == 0) ? 1 : 0;
    }
    int idx = blockIdx.x * blockDim.x + threadIdx.x;
    if (idx >= N_NODES * HID) return;
    int i = idx >> 6, j = idx & 63;
    float acc = b[j]
              + x[i * 3 + 0] * W[j * 3 + 0]
              + x[i * 3 + 1] * W[j * 3 + 1]
              + x[i * 3 + 2] * W[j * 3 + 2];
    h16[idx] = __float2half(fmaxf(acc, 0.0f));
}

// ---------------- one-pass bucketed CSR build ----------------
__global__ void k_scatter(const void* __restrict__ eptr) {
    long long e = (long long)blockIdx.x * blockDim.x + threadIdx.x;
    if (e >= N_EDGES) return;
    int is64 = g_is64;
    int s = edge_at(eptr, e, is64);
    int d = edge_at(eptr, (long long)N_EDGES + e, is64);
    int pos = atomicAdd(&g_cnt[d], 1);
    if (pos < CAP) g_csr[d * CAP + pos] = s;
}

// ---------------- aggregation: fp16 gather, fp32 accumulate ----------------
template <int LAST>
__global__ void __launch_bounds__(256) k_agg(const __half* __restrict__ h16) {
    int gtid = blockIdx.x * blockDim.x + threadIdx.x;
    int node = gtid >> 4;
    int sub = gtid & 15;
    if (node >= N_NODES) return;
    int cnt = g_cnt[node];
    if (cnt > CAP) cnt = CAP;
    const int* __restrict__ lst = &g_csr[node * CAP];
    const uint2* __restrict__ hv = (const uint2*)h16;
    float4 acc = make_float4(0.f, 0.f, 0.f, 0.f);
    int k = 0;
    for (; k + 8 <= cnt; k += 8) {
        uint2 r[8];
#pragma unroll
        for (int q = 0; q < 8; q++)
            r[q] = __ldg(&hv[lst[k + q] * 16 + sub]);
#pragma unroll
        for (int q = 0; q < 8; q++) {
            float2 f0 = __half22float2(*(__half2*)&r[q].x);
            float2 f1 = __half22float2(*(__half2*)&r[q].y);
            acc.x += f0.x; acc.y += f0.y; acc.z += f1.x; acc.w += f1.y;
        }
    }
    for (; k < cnt; k++) {
        uint2 raw = __ldg(&hv[lst[k] * 16 + sub]);
        float2 f0 = __half22float2(*(__half2*)&raw.x);
        float2 f1 = __half22float2(*(__half2*)&raw.y);
        acc.x += f0.x; acc.y += f0.y; acc.z += f1.x; acc.w += f1.y;
    }
    ((float4*)g_agg)[node * 16 + sub] = acc;
    if (LAST && sub == 0) g_cnt[node] = 0;
}

// ---------------- transform via fp16 m16n8k16 mma + ldmatrix B loads ----------------
// hout16 = relu([agg|h16in] @ [relW|rootW].T + relb); LAST fuses post-MLP -> out fp32.
// agg k-steps: hi/lo split (3 mmas); root k-steps: exact fp16 (2 mmas).
// B fragments fetched with ldmatrix.x4 (2 n-tiles per instruction); WPAD=68 -> conflict-free.
#define WPAD 68
#define SPAD 66
#define XF_SMEM0 (2 * 64 * WPAD * 4)                       // 34816 B
#define XF_SMEM1 (2 * 64 * WPAD * 4 + 8 * 16 * SPAD * 4)   // 68608 B

template <int LAST>
__global__ void __launch_bounds__(256, 3) k_xf(
        const __half* __restrict__ h16in,
        const float* __restrict__ relW, const float* __restrict__ relb,
        const float* __restrict__ rootW,
        const float* __restrict__ postW, const float* __restrict__ postb,
        float* __restrict__ out, __half* __restrict__ hout16) {
    extern __shared__ uint32_t smemu[];
    uint32_t* sBh = smemu;                 // [64 n][64 kp] packed half2, stride WPAD
    uint32_t* sBl = smemu + 64 * WPAD;
    float* sSt = (float*)(smemu + 2 * 64 * WPAD);   // LAST only
    const int tid = threadIdx.x;
    const int warp = tid >> 5;
    const int lane = tid & 31;

    // --- stage combined weights as packed half2 hi/lo (float4 granularity) ---
    for (int f = tid; f < 64 * 32; f += 256) {
        int n = f >> 5, kp2 = (f & 31) * 2;
        int k = kp2 * 2;
        const float* src = (k < 64) ? &relW[n * 64 + k] : &rootW[n * 64 + (k - 64)];
        float4 v = *(const float4*)src;
        uint32_t hi0 = pkh(v.x, v.y);
        uint32_t hi1 = pkh(v.z, v.w);
        sBh[n * WPAD + kp2]     = hi0;
        sBh[n * WPAD + kp2 + 1] = hi1;
        sBl[n * WPAD + kp2]     = pklo(v.x, v.y, hi0);
        sBl[n * WPAD + kp2 + 1] = pklo(v.z, v.w, hi1);
    }
    __syncthreads();

    const int qr = lane >> 2;
    const int qc = lane & 3;
    const int r0 = blockIdx.x * 128 + warp * 16 + qr;
    const int r1 = r0 + 8;
    const int r0c = (r0 < N_NODES) ? r0 : (N_NODES - 1);
    const int r1c = (r1 < N_NODES) ? r1 : (N_NODES - 1);
    const float* __restrict__ aggr0 = &g_agg[(size_t)r0c * 64];
    const float* __restrict__ aggr1 = &g_agg[(size_t)r1c * 64];
    const __half* __restrict__ hr0 = &h16in[(size_t)r0c * 64];
    const __half* __restrict__ hr1 = &h16in[(size_t)r1c * 64];

    // ldmatrix per-lane row addresses: group g = lane>>3 selects (nt-half, b0/b1)
    const int grp = lane >> 3, wi = lane & 7;
    const uint32_t rowoff = (uint32_t)((((grp >> 1) * 8 + wi) * WPAD + (grp & 1) * 4) * 4);
    const uint32_t hrow = smem_u32(sBh) + rowoff;
    const uint32_t lrow = smem_u32(sBl) + rowoff;

    float d[8][4];
#pragma unroll
    for (int nt = 0; nt < 8; nt++)
#pragma unroll
        for (int i = 0; i < 4; i++) d[nt][i] = 0.f;

    // --- software-pipelined agg k-steps (ks 0..3): hi/lo split, 3 mmas ---
    float2 pa0 = __ldg((const float2*)&aggr0[2 * qc]);
    float2 pa1 = __ldg((const float2*)&aggr1[2 * qc]);
    float2 pa2 = __ldg((const float2*)&aggr0[2 * qc + 8]);
    float2 pa3 = __ldg((const float2*)&aggr1[2 * qc + 8]);
    uint32_t pr0, pr1, pr2, pr3;
#pragma unroll
    for (int ks = 0; ks < 4; ks++) {
        float2 f0 = pa0, f1 = pa1, f2 = pa2, f3 = pa3;
        if (ks < 3) {
            const int kc = (ks + 1) * 16 + 2 * qc;
            pa0 = __ldg((const float2*)&aggr0[kc]);
            pa1 = __ldg((const float2*)&aggr1[kc]);
            pa2 = __ldg((const float2*)&aggr0[kc + 8]);
            pa3 = __ldg((const float2*)&aggr1[kc + 8]);
        } else {
            const int kc = 2 * qc;
            pr0 = __ldg((const uint32_t*)&hr0[kc]);
            pr1 = __ldg((const uint32_t*)&hr1[kc]);
            pr2 = __ldg((const uint32_t*)&hr0[kc + 8]);
            pr3 = __ldg((const uint32_t*)&hr1[kc + 8]);
        }
        uint32_t ah0 = pkh(f0.x, f0.y), ah1 = pkh(f1.x, f1.y);
        uint32_t ah2 = pkh(f2.x, f2.y), ah3 = pkh(f3.x, f3.y);
        uint32_t al0 = pklo(f0.x, f0.y, ah0), al1 = pklo(f1.x, f1.y, ah1);
        uint32_t al2 = pklo(f2.x, f2.y, ah2), al3 = pklo(f3.x, f3.y, ah3);

        const uint32_t ko = (uint32_t)(ks * 32);   // (ks*8)*4 bytes
#pragma unroll
        for (int p = 0; p < 4; p++) {
            const uint32_t off = (uint32_t)(p * 16 * WPAD * 4) + ko;
            uint32_t bh0, bh1, bh2, bh3, bl0, bl1, bl2, bl3;
            LDSM_X4(bh0, bh1, bh2, bh3, hrow + off);
            LDSM_X4(bl0, bl1, bl2, bl3, lrow + off);
            mma16(d[2 * p],     ah0, ah1, ah2, ah3, bh0, bh1);
            mma16(d[2 * p],     al0, al1, al2, al3, bh0, bh1);
            mma16(d[2 * p],     ah0, ah1, ah2, ah3, bl0, bl1);
            mma16(d[2 * p + 1], ah0, ah1, ah2, ah3, bh2, bh3);
            mma16(d[2 * p + 1], al0, al1, al2, al3, bh2, bh3);
            mma16(d[2 * p + 1], ah0, ah1, ah2, ah3, bl2, bl3);
        }
    }

    // --- software-pipelined root k-steps (ks 4..7): exact fp16, 2 mmas ---
#pragma unroll
    for (int ks = 4; ks < 8; ks++) {
        uint32_t ah0 = pr0, ah1 = pr1, ah2 = pr2, ah3 = pr3;
        if (ks < 7) {
            const int kc = (ks - 3) * 16 + 2 * qc;
            pr0 = __ldg((const uint32_t*)&hr0[kc]);
            pr1 = __ldg((const uint32_t*)&hr1[kc]);
            pr2 = __ldg((const uint32_t*)&hr0[kc + 8]);
            pr3 = __ldg((const uint32_t*)&hr1[kc + 8]);
        }
        const uint32_t ko = (uint32_t)(ks * 32);
#pragma unroll
        for (int p = 0; p < 4; p++) {
            const uint32_t off = (uint32_t)(p * 16 * WPAD * 4) + ko;
            uint32_t bh0, bh1, bh2, bh3, bl0, bl1, bl2, bl3;
            LDSM_X4(bh0, bh1, bh2, bh3, hrow + off);
            LDSM_X4(bl0, bl1, bl2, bl3, lrow + off);
            mma16(d[2 * p],     ah0, ah1, ah2, ah3, bh0, bh1);
            mma16(d[2 * p],     ah0, ah1, ah2, ah3, bl0, bl1);
            mma16(d[2 * p + 1], ah0, ah1, ah2, ah3, bh2, bh3);
            mma16(d[2 * p + 1], ah0, ah1, ah2, ah3, bl2, bl3);
        }
    }

    if (!LAST) {
#pragma unroll
        for (int nt = 0; nt < 8; nt++) {
            const int col = nt * 8 + 2 * qc;
            const float bx = __ldg(&relb[col]);
            const float by = __ldg(&relb[col + 1]);
            if (r0 < N_NODES) {
                float vx = fmaxf(d[nt][0] + bx, 0.f), vy = fmaxf(d[nt][1] + by, 0.f);
                *(__half2*)&hout16[(size_t)r0 * 64 + col] = __floats2half2_rn(vx, vy);
            }
            if (r1 < N_NODES) {
                float vx = fmaxf(d[nt][2] + bx, 0.f), vy = fmaxf(d[nt][3] + by, 0.f);
                *(__half2*)&hout16[(size_t)r1 * 64 + col] = __floats2half2_rn(vx, vy);
            }
        }
    } else {
        float* st = sSt + warp * 16 * SPAD;
#pragma unroll
        for (int nt = 0; nt < 8; nt++) {
            const int col = nt * 8 + 2 * qc;
            const float bx = __ldg(&relb[col]);
            const float by = __ldg(&relb[col + 1]);
            st[qr * SPAD + col]           = fmaxf(d[nt][0] + bx, 0.f);
            st[qr * SPAD + col + 1]       = fmaxf(d[nt][1] + by, 0.f);
            st[(qr + 8) * SPAD + col]     = fmaxf(d[nt][2] + bx, 0.f);
            st[(qr + 8) * SPAD + col + 1] = fmaxf(d[nt][3] + by, 0.f);
        }
        __syncwarp();
        if (lane < 16) {
            const int gr = blockIdx.x * 128 + warp * 16 + lane;
            if (gr < N_NODES) {
                float o0 = __ldg(&postb[0]), o1 = __ldg(&postb[1]);
                const float* row = &st[lane * SPAD];
#pragma unroll 8
                for (int c = 0; c < 64; c++) {
                    float v = row[c];
                    o0 += v * __ldg(&postW[c]);
                    o1 += v * __ldg(&postW[64 + c]);
                }
                out[2 * gr + 0] = fmaxf(o0, 0.f);
                out[2 * gr + 1] = fmaxf(o1, 0.f);
            }
        }
    }
}

// ---------------- launch (8 kernels) ----------------
extern "C" void kernel_launch(void* const* d_in, const int* in_sizes, int n_in,
                              void* d_out, int out_size) {
    const float* x     = (const float*)d_in[0];
    const void*  ei    = d_in[1];
    const float* preW  = (const float*)d_in[2];
    const float* preb  = (const float*)d_in[3];
    const float* postW = (const float*)d_in[4];
    const float* postb = (const float*)d_in[5];
    const float* relW[3]  = {(const float*)d_in[6],  (const float*)d_in[9],  (const float*)d_in[12]};
    const float* relb[3]  = {(const float*)d_in[7],  (const float*)d_in[10], (const float*)d_in[13]};
    const float* rootW[3] = {(const float*)d_in[8],  (const float*)d_in[11], (const float*)d_in[14]};
    float* out = (float*)d_out;

    cudaFuncSetAttribute(k_xf<0>, cudaFuncAttributeMaxDynamicSharedMemorySize, XF_SMEM0);
    cudaFuncSetAttribute(k_xf<1>, cudaFuncAttributeMaxDynamicSharedMemorySize, XF_SMEM1);

    __half *h16A, *h16B;
    cudaGetSymbolAddress((void**)&h16A, g_h16A);
    cudaGetSymbolAddress((void**)&h16B, g_h16B);

    // 1. pre-MLP (+ edge dtype detect in block 0)
    k_pre<<<(N_NODES * HID + 255) / 256, 256>>>(x, preW, preb, h16A, (const int*)ei);
    // 2. one-pass bucketed CSR build
    k_scatter<<<(N_EDGES + 255) / 256, 256>>>(ei);

    const int agg_blocks = (N_NODES * 16 + 255) / 256;
    const int xf_blocks  = (N_NODES + 127) / 128;

    // 3-8. layer 0: A -> B ; layer 1: B -> A ; layer 2 (last, fused post): A -> out
    k_agg<0><<<agg_blocks, 256>>>(h16A);
    k_xf<0><<<xf_blocks, 256, XF_SMEM0>>>(h16A, relW[0], relb[0], rootW[0], postW, postb, out, h16B);
    k_agg<0><<<agg_blocks, 256>>>(h16B);
    k_xf<0><<<xf_blocks, 256, XF_SMEM0>>>(h16B, relW[1], relb[1], rootW[1], postW, postb, out, h16A);
    k_agg<1><<<agg_blocks, 256>>>(h16A);   // zeros g_cnt after final read
    k_xf<1><<<xf_blocks, 256, XF_SMEM1>>>(h16A, relW[2], relb[2], rootW[2], postW, postb, out, h16B);
}